// round 6
// baseline (speedup 1.0000x reference)
#include <cuda_runtime.h>

#define N_UE 8192

// Device globals (alloc-free rule)
__device__ float2 U16g[3][16][16];   // update-block 16x16 unitaries (bits: q3=8, anc=4, q7=2, q8=1)
__device__ float2 RAg[16][8][8];     // T0 applied to basis: [(m0*4+k)][p][q]
__device__ float2 RBg[64][8][8];     // T1 applied: [(m1*16+m0*4+k)][p][q]
__device__ float  Cg[768];           // C[a*256 + m2*64 + m1*16 + m0*4 + k]
__device__ float  g_strong[32];      // fused strong-block 4x4 complex unitary, row-major (idx = 2*b_e + b_nb)

// Hermitian basis G_m entry tables: G0=E00, G1=E11, G2=E01+E10, G3=i*E01-i*E10
__constant__ int   cGN[4]     = {1, 1, 2, 2};
__constant__ int   cGa[4][2]  = {{0,0},{1,0},{0,1},{0,1}};
__constant__ int   cGb[4][2]  = {{0,0},{1,0},{1,0},{1,0}};
__constant__ float cGwr[4][2] = {{1,0},{1,0},{1,1},{0,0}};
__constant__ float cGwi[4][2] = {{0,0},{0,0},{0,0},{1,-1}};

__device__ __forceinline__ float2 cadd2(float2 a, float2 b) { return make_float2(a.x + b.x, a.y + b.y); }
__device__ __forceinline__ float2 cmul2(float2 a, float2 b) {
    return make_float2(a.x * b.x - a.y * b.y, a.x * b.y + a.y * b.x);
}
__device__ __forceinline__ float2 cmulc(float2 a, float2 b) {   // a * conj(b)
    return make_float2(a.x * b.x + a.y * b.y, a.y * b.x - a.x * b.y);
}
__device__ __forceinline__ float lrelu(float v) { return v > 0.f ? v : 0.01f * v; }

// system s = 4*b3 + 2*b7 + b8 ; full 4-qubit index with ancilla bit a
__device__ __forceinline__ int fidx(int s, int a) { return ((s & 4) << 1) | (a << 2) | (s & 3); }

__device__ __forceinline__ void rot_to(float* o, float phi, float th, float om)
{
    float c, s, cp, sp, cm, sm;
    __sincosf(0.5f * th, &s, &c);
    __sincosf(0.5f * (phi + om), &sp, &cp);
    __sincosf(0.5f * (phi - om), &sm, &cm);
    o[0] =  c * cp; o[1] = -c * sp;
    o[2] = -s * cm; o[3] = -s * sm;
    o[4] =  s * cm; o[5] = -s * sm;
    o[6] =  c * cp; o[7] =  c * sp;
}

struct cplx { float r, i; };
__device__ void rot2c(cplx* o, float phi, float th, float om)
{
    float m[8]; rot_to(m, phi, th, om);
    o[0] = cplx{m[0], m[1]}; o[1] = cplx{m[2], m[3]};
    o[2] = cplx{m[4], m[5]}; o[3] = cplx{m[6], m[7]};
}
__device__ void lmul4(cplx* U, const cplx* G)   // U <- G @ U
{
    cplx T[16];
    for (int i = 0; i < 4; i++)
        for (int j = 0; j < 4; j++) {
            cplx s{0.f, 0.f};
            for (int k = 0; k < 4; k++) {
                cplx g = G[i * 4 + k], u = U[k * 4 + j];
                s.r += g.r * u.r - g.i * u.i;
                s.i += g.r * u.i + g.i * u.r;
            }
            T[i * 4 + j] = s;
        }
    for (int i = 0; i < 16; i++) U[i] = T[i];
}
__device__ __forceinline__ void zero16(cplx* G) { for (int i = 0; i < 16; i++) G[i] = cplx{0.f, 0.f}; }

// ---------------------------------------------------------------------------
// K0 (1 block, 64 thr): build U16 columns (t<48) and strong 4x4 (t==48).
// ---------------------------------------------------------------------------
__global__ __launch_bounds__(64)
void k_setup0(const float* __restrict__ strong,
              const float* __restrict__ inits,
              const float* __restrict__ update)
{
    int t = threadIdx.x;

    if (t < 48) {
        int i = t >> 4, col = t & 15;
        float2 v[16];
#pragma unroll
        for (int x = 0; x < 16; x++) v[x] = make_float2(x == col ? 1.f : 0.f, 0.f);
        for (int l = 0; l < 2; l++) {
            for (int j = 0; j < 4; j++) {
                float m[8];
                const float* w = update + ((i * 2 + l) * 4 + j) * 3;
                rot_to(m, w[0], w[1], w[2]);
                int M = 8 >> j;
                for (int x = 0; x < 16; x++) if (!(x & M)) {
                    int x1 = x | M;
                    float2 a0 = v[x], a1 = v[x1];
                    v[x]  = make_float2(m[0]*a0.x - m[1]*a0.y + m[2]*a1.x - m[3]*a1.y,
                                        m[0]*a0.y + m[1]*a0.x + m[2]*a1.y + m[3]*a1.x);
                    v[x1] = make_float2(m[4]*a0.x - m[5]*a0.y + m[6]*a1.x - m[7]*a1.y,
                                        m[4]*a0.y + m[5]*a0.x + m[6]*a1.y + m[7]*a1.x);
                }
            }
            const int cm4[4] = {8, 4, 2, 1};
            const int t0m[4] = {4, 2, 1, 8};   // l=0: r=1
            const int t1m[4] = {2, 1, 8, 4};   // l=1: r=2
            for (int j = 0; j < 4; j++) {
                int cm = cm4[j], tm = l ? t1m[j] : t0m[j];
                for (int x = 0; x < 16; x++)
                    if ((x & cm) && (x & tm)) {
                        float2 tmp = v[x]; v[x] = v[x ^ tm]; v[x ^ tm] = tmp;
                    }
            }
        }
        for (int row = 0; row < 16; row++) U16g[i][row][col] = v[row];
    }

    if (t == 48) {
        cplx U[16], G[16], r2[4];
        zero16(U); U[0] = U[5] = U[10] = U[15] = cplx{1.f, 0.f};
        float c, s;
        __sincosf(0.5f * inits[0], &s, &c);        // CRX control=nb target=e
        zero16(G);
        G[0] = cplx{1.f,0.f}; G[10] = cplx{1.f,0.f};
        G[5] = cplx{c,0.f};   G[7]  = cplx{0.f,-s};
        G[13] = cplx{0.f,-s}; G[15] = cplx{c,0.f};
        lmul4(U, G);
        __sincosf(0.5f * inits[1], &s, &c);        // CRY control=e target=nb
        zero16(G);
        G[0] = cplx{1.f,0.f}; G[5] = cplx{1.f,0.f};
        G[10] = cplx{c,0.f};  G[11] = cplx{-s,0.f};
        G[14] = cplx{s,0.f};  G[15] = cplx{c,0.f};
        lmul4(U, G);
        for (int l = 0; l < 2; l++) {
            rot2c(r2, strong[(l*2+0)*3], strong[(l*2+0)*3+1], strong[(l*2+0)*3+2]);  // ROT on e
            zero16(G);
            G[0] = r2[0]; G[2] = r2[1]; G[8] = r2[2]; G[10] = r2[3];
            G[5] = r2[0]; G[7] = r2[1]; G[13] = r2[2]; G[15] = r2[3];
            lmul4(U, G);
            rot2c(r2, strong[(l*2+1)*3], strong[(l*2+1)*3+1], strong[(l*2+1)*3+2]);  // ROT on nb
            zero16(G);
            G[0] = r2[0]; G[1] = r2[1]; G[4] = r2[2]; G[5] = r2[3];
            G[10] = r2[0]; G[11] = r2[1]; G[14] = r2[2]; G[15] = r2[3];
            lmul4(U, G);
            zero16(G);                                         // CX e->nb: swap 2<->3
            G[0] = cplx{1.f,0.f}; G[5] = cplx{1.f,0.f};
            G[11] = cplx{1.f,0.f}; G[14] = cplx{1.f,0.f};
            lmul4(U, G);
            zero16(G);                                         // CX nb->e: swap 1<->3
            G[0] = cplx{1.f,0.f}; G[10] = cplx{1.f,0.f};
            G[7] = cplx{1.f,0.f}; G[13] = cplx{1.f,0.f};
            lmul4(U, G);
        }
        for (int x = 0; x < 16; x++) {
            g_strong[x * 2 + 0] = U[x].r;
            g_strong[x * 2 + 1] = U[x].i;
        }
    }
}

// ---------------------------------------------------------------------------
// K1 (4 blocks x 256): RA[m0*4+k][p][q] = T0(F_k ; G_m0)
// ---------------------------------------------------------------------------
__global__ __launch_bounds__(256)
void k_setup1b()
{
    int t = blockIdx.x * 256 + threadIdx.x;       // [0, 1024)
    int m0 = (t >> 8) & 3, k = (t >> 6) & 3, p = (t >> 3) & 7, q = t & 7;
    float2 acc = make_float2(0.f, 0.f);
    for (int a = 0; a < 2; a++) {
        int rp = fidx(p, a), rq = fidx(q, a);
        for (int ef = 0; ef < cGN[k]; ef++) {
            int ps = 4 * cGa[k][ef], qs = 4 * cGb[k][ef];
            float2 wf = make_float2(cGwr[k][ef], cGwi[k][ef]);
            for (int eg = 0; eg < cGN[m0]; eg++) {
                float2 wg = make_float2(cGwr[m0][eg], cGwi[m0][eg]);
                float2 u1 = U16g[0][rp][fidx(ps, cGa[m0][eg])];
                float2 u2 = U16g[0][rq][fidx(qs, cGb[m0][eg])];
                acc = cadd2(acc, cmul2(cmul2(wf, wg), cmulc(u1, u2)));
            }
        }
    }
    RAg[m0 * 4 + k][p][q] = acc;
}

// ---------------------------------------------------------------------------
// K2 (16 blocks x 256): RB[m1*16+m0*4+k] = T1(RA[m0*4+k] ; G_m1)
// ---------------------------------------------------------------------------
__global__ __launch_bounds__(256)
void k_setup2()
{
    int id = blockIdx.x * 256 + threadIdx.x;      // [0, 4096)
    int m1 = id >> 10, c0 = (id >> 6) & 15, p = (id >> 3) & 7, q = id & 7;
    const float2 (*RA)[8] = RAg[c0];

    float2 acc = make_float2(0.f, 0.f);
    for (int a = 0; a < 2; a++) {
        int rp = fidx(p, a), rq = fidx(q, a);
        for (int eg = 0; eg < cGN[m1]; eg++) {
            float2 w = make_float2(cGwr[m1][eg], cGwi[m1][eg]);
            int al = cGa[m1][eg], ar = cGb[m1][eg];
            float2 ssum = make_float2(0.f, 0.f);
            for (int ps = 0; ps < 8; ps++) {
                float2 up = U16g[1][rp][fidx(ps, al)];
                float2 ts = make_float2(0.f, 0.f);
                for (int qs = 0; qs < 8; qs++)
                    ts = cadd2(ts, cmulc(RA[ps][qs], U16g[1][rq][fidx(qs, ar)]));
                ssum = cadd2(ssum, cmul2(up, ts));
            }
            acc = cadd2(acc, cmul2(w, ssum));
        }
    }
    RBg[m1 * 16 + c0][p][q] = acc;
}

// ---------------------------------------------------------------------------
// K3 (1 block x 256): diag of T2(RB ; G_m2) for 256 combos, then Z-contract.
// Each thread handles 8 diag entries (one combo's full diagonal).
// ---------------------------------------------------------------------------
__global__ __launch_bounds__(256)
void k_setup3()
{
    __shared__ float diag_sh[2048];
    int t = threadIdx.x;
    {
        int combo = t;                 // [0, 256)
        int m2 = combo >> 6, c3 = combo & 63;
        const float2 (*RB)[8] = RBg[c3];
        for (int p = 0; p < 8; p++) {
            float2 acc = make_float2(0.f, 0.f);
            for (int a = 0; a < 2; a++) {
                int rp = fidx(p, a);
                for (int eg = 0; eg < cGN[m2]; eg++) {
                    float2 w = make_float2(cGwr[m2][eg], cGwi[m2][eg]);
                    int al = cGa[m2][eg], ar = cGb[m2][eg];
                    float2 ssum = make_float2(0.f, 0.f);
                    for (int ps = 0; ps < 8; ps++) {
                        float2 up = U16g[2][rp][fidx(ps, al)];
                        float2 ts = make_float2(0.f, 0.f);
                        for (int qs = 0; qs < 8; qs++)
                            ts = cadd2(ts, cmulc(RB[ps][qs], U16g[2][rp][fidx(qs, ar)]));
                        ssum = cadd2(ssum, cmul2(up, ts));
                    }
                    acc = cadd2(acc, cmul2(w, ssum));
                }
            }
            diag_sh[combo * 8 + p] = acc.x;
        }
    }
    __syncthreads();

    // 768 outputs, 256 threads -> 3 each
    for (int a = 0; a < 3; a++) {
        int combo = t;
        float s = 0.f;
        for (int p = 0; p < 8; p++) {
            int bit = (a == 0) ? (p & 4) : (a == 1) ? (p & 2) : (p & 1);
            s += (bit ? -1.f : 1.f) * diag_sh[combo * 8 + p];
        }
        Cg[a * 256 + combo] = s;
    }
}

// ---------------------------------------------------------------------------
// Warp-cooperative MLP row: x (D floats) -> 2 outputs (same on all lanes)
// ---------------------------------------------------------------------------
template <int D>
__device__ __forceinline__ float2 mlp_row(const float* __restrict__ x,
                                          const float* __restrict__ W1, const float* __restrict__ b1,
                                          const float* __restrict__ W2, const float* __restrict__ b2,
                                          int lane)
{
    float xv[D];
#pragma unroll
    for (int d = 0; d < D; d++) xv[d] = __ldg(x + d);
    float o0 = 0.f, o1 = 0.f;
#pragma unroll
    for (int r = 0; r < 4; r++) {
        int d = lane + 32 * r;
        float h = __ldg(b1 + d);
#pragma unroll
        for (int k = 0; k < D; k++) h = fmaf(xv[k], __ldg(W1 + k * 128 + d), h);
        h = lrelu(h);
        float2 w2 = __ldg((const float2*)(W2 + d * 2));
        o0 = fmaf(h, w2.x, o0);
        o1 = fmaf(h, w2.y, o1);
    }
#pragma unroll
    for (int o = 16; o; o >>= 1) {
        o0 += __shfl_xor_sync(0xFFFFFFFFu, o0, o);
        o1 += __shfl_xor_sync(0xFFFFFFFFu, o1, o);
    }
    return make_float2(o0 + __ldg(b2), o1 + __ldg(b2 + 1));
}

// ---------------------------------------------------------------------------
// Mega kernel: embeddings -> analytic channel contraction -> classifier head.
// ---------------------------------------------------------------------------
__global__ __launch_bounds__(256)
void mega_kernel(const float* __restrict__ x_ue, const float* __restrict__ x_ap,
                 const float* __restrict__ edge_attr, const int* __restrict__ edge_src,
                 const float* __restrict__ Wn1u, const float* __restrict__ bn1u,
                 const float* __restrict__ Wn2u, const float* __restrict__ bn2u,
                 const float* __restrict__ Wn1a, const float* __restrict__ bn1a,
                 const float* __restrict__ Wn2a, const float* __restrict__ bn2a,
                 const float* __restrict__ We1,  const float* __restrict__ be1,
                 const float* __restrict__ We2,  const float* __restrict__ be2,
                 const float* __restrict__ Wu1,  const float* __restrict__ bu1,
                 const float* __restrict__ Wu2,  const float* __restrict__ bu2,
                 const float* __restrict__ ln_g, const float* __restrict__ ln_b,
                 const float* __restrict__ Wf1,  const float* __restrict__ bf1,
                 const float* __restrict__ Wf2,  const float* __restrict__ bf2,
                 const float* __restrict__ Wf3,  const float* __restrict__ bf3,
                 float* __restrict__ out)
{
    int warp = threadIdx.x >> 5;
    int lane = threadIdx.x & 31;
    int n = blockIdx.x * 8 + warp;

    // ---- Phase 1: embeddings ----------------------------------------------
    float a[7], b[7];
#pragma unroll
    for (int q = 0; q < 3; q++) {
        float2 e = mlp_row<4>(edge_attr + (n * 3 + q) * 4, We1, be1, We2, be2, lane);
        a[q] = e.x; b[q] = e.y;
    }
    {
        float2 u = mlp_row<8>(x_ue + n * 8, Wn1u, bn1u, Wn2u, bn2u, lane);
        a[3] = u.x; b[3] = u.y;
    }
#pragma unroll
    for (int i = 0; i < 3; i++) {
        int src = __ldg(&edge_src[n * 3 + i]);
        float2 p = mlp_row<8>(x_ap + src * 8, Wn1a, bn1a, Wn2a, bn2a, lane);
        a[4 + i] = p.x; b[4 + i] = p.y;
    }

    // ---- Phase 2: analytic quantum channel ---------------------------------
    float2 sq[7][2];
#pragma unroll
    for (int q = 0; q < 7; q++) {
        float ca, sa, cb2, sb2;
        __sincosf(0.5f * a[q], &sa, &ca);
        __sincosf(0.5f * b[q], &sb2, &cb2);
        sq[q][0] = make_float2(ca * cb2, -ca * sb2);
        sq[q][1] = make_float2(sa * sb2, -sa * cb2);
    }

    float f0[4];
    {
        float2 u0 = sq[3][0], u1 = sq[3][1];
        f0[0] = u0.x * u0.x + u0.y * u0.y;
        f0[1] = u1.x * u1.x + u1.y * u1.y;
        float2 x01 = cmulc(u0, u1);
        f0[2] = x01.x; f0[3] = x01.y;
    }

    float2 V[16];
    {
        const float4* gp = (const float4*)g_strong;
#pragma unroll
        for (int h = 0; h < 8; h++) {
            float4 x = __ldg(gp + h);
            V[2 * h]     = make_float2(x.x, x.y);
            V[2 * h + 1] = make_float2(x.z, x.w);
        }
    }

    float g[3][4];
#pragma unroll
    for (int i = 0; i < 3; i++) {
        float2 e0 = sq[i][0], e1 = sq[i][1], n0 = sq[4 + i][0], n1 = sq[4 + i][1];
        float2 in4[4] = {cmul2(e0, n0), cmul2(e0, n1), cmul2(e1, n0), cmul2(e1, n1)};
        float2 chi[4];
#pragma unroll
        for (int r = 0; r < 4; r++) {
            float2 s = cmul2(V[r * 4 + 0], in4[0]);
            s = cadd2(s, cmul2(V[r * 4 + 1], in4[1]));
            s = cadd2(s, cmul2(V[r * 4 + 2], in4[2]));
            s = cadd2(s, cmul2(V[r * 4 + 3], in4[3]));
            chi[r] = s;
        }
        // reduced ancilla (nb) state: rho = Tr_e |chi><chi| ; basis idx = 2*b_e + b_nb
        g[i][0] = chi[0].x*chi[0].x + chi[0].y*chi[0].y + chi[2].x*chi[2].x + chi[2].y*chi[2].y;
        g[i][1] = chi[1].x*chi[1].x + chi[1].y*chi[1].y + chi[3].x*chi[3].x + chi[3].y*chi[3].y;
        float2 x01 = cadd2(cmulc(chi[0], chi[1]), cmulc(chi[2], chi[3]));
        g[i][2] = x01.x; g[i][3] = x01.y;
    }

    // contraction: combo c = m2*64 + m1*16 + m0*4 + k ; lane handles c = lane + 32j
    float m3 = 0.f, m7 = 0.f, m8 = 0.f;
#pragma unroll
    for (int j = 0; j < 8; j++) {
        int c = lane + 32 * j;
        float prod = f0[c & 3] * g[0][(c >> 2) & 3] * g[1][(c >> 4) & 3] * g[2][(c >> 6) & 3];
        m3 = fmaf(prod, __ldg(&Cg[c]),       m3);
        m7 = fmaf(prod, __ldg(&Cg[256 + c]), m7);
        m8 = fmaf(prod, __ldg(&Cg[512 + c]), m8);
    }
#pragma unroll
    for (int o = 16; o; o >>= 1) {
        m3 += __shfl_xor_sync(0xFFFFFFFFu, m3, o);
        m7 += __shfl_xor_sync(0xFFFFFFFFu, m7, o);
        m8 += __shfl_xor_sync(0xFFFFFFFFu, m8, o);
    }

    // ---- Phase 3: classifier head ------------------------------------------
    float in5[5] = {a[3], b[3], m3, m7, m8};

    float u0 = 0.f, u1 = 0.f;
#pragma unroll
    for (int r = 0; r < 4; r++) {
        int d = lane + 32 * r;
        float h = __ldg(bu1 + d);
#pragma unroll
        for (int k = 0; k < 5; k++) h = fmaf(in5[k], __ldg(Wu1 + k * 128 + d), h);
        h = lrelu(h);
        float2 w2 = __ldg((const float2*)(Wu2 + d * 2));
        u0 = fmaf(h, w2.x, u0);
        u1 = fmaf(h, w2.y, u1);
    }
#pragma unroll
    for (int o = 16; o; o >>= 1) {
        u0 += __shfl_xor_sync(0xFFFFFFFFu, u0, o);
        u1 += __shfl_xor_sync(0xFFFFFFFFu, u1, o);
    }
    float h0 = in5[0] + u0 + __ldg(bu2);
    float h1 = in5[1] + u1 + __ldg(bu2 + 1);

    float mu = 0.5f * (h0 + h1);
    float d0 = h0 - mu, d1 = h1 - mu;
    float var = 0.5f * (d0 * d0 + d1 * d1);
    float inv = rsqrtf(var + 1e-5f);
    h0 = d0 * inv * __ldg(ln_g) + __ldg(ln_b);
    h1 = d1 * inv * __ldg(ln_g + 1) + __ldg(ln_b + 1);

    float av[4];
#pragma unroll
    for (int r = 0; r < 4; r++) {
        int d = lane + 32 * r;
        av[r] = lrelu(fmaf(h0, __ldg(Wf1 + d), fmaf(h1, __ldg(Wf1 + 128 + d), __ldg(bf1 + d))));
    }

    float bv[4];
#pragma unroll
    for (int r = 0; r < 4; r++) bv[r] = __ldg(bf2 + lane + 32 * r);
    for (int k = 0; k < 128; k++) {
        float ak = __shfl_sync(0xFFFFFFFFu, av[k >> 5], k & 31);
        const float* row = Wf2 + k * 128;
#pragma unroll
        for (int r = 0; r < 4; r++) bv[r] = fmaf(ak, __ldg(row + lane + 32 * r), bv[r]);
    }

    float o0 = 0.f, o1 = 0.f;
#pragma unroll
    for (int r = 0; r < 4; r++) {
        int d = lane + 32 * r;
        float t = lrelu(bv[r]);
        float2 w3 = __ldg((const float2*)(Wf3 + d * 2));
        o0 = fmaf(t, w3.x, o0);
        o1 = fmaf(t, w3.y, o1);
    }
#pragma unroll
    for (int o = 16; o; o >>= 1) {
        o0 += __shfl_xor_sync(0xFFFFFFFFu, o0, o);
        o1 += __shfl_xor_sync(0xFFFFFFFFu, o1, o);
    }
    if (lane == 0) {
        o0 += __ldg(bf3);
        o1 += __ldg(bf3 + 1);
        out[n * 2 + 0] = 1.f / (1.f + __expf(-o0));
        out[n * 2 + 1] = 1.f / (1.f + __expf(-o1));
    }
}

// ---------------------------------------------------------------------------
extern "C" void kernel_launch(void* const* d_in, const int* in_sizes, int n_in,
                              void* d_out, int out_size)
{
    (void)in_sizes; (void)n_in; (void)out_size;
    const float* x_ue      = (const float*)d_in[0];
    const float* x_ap      = (const float*)d_in[1];
    const float* edge_attr = (const float*)d_in[2];
    const int*   edge_src  = (const int*)  d_in[3];
    const float* Wn1u = (const float*)d_in[5];
    const float* bn1u = (const float*)d_in[6];
    const float* Wn2u = (const float*)d_in[7];
    const float* bn2u = (const float*)d_in[8];
    const float* Wn1a = (const float*)d_in[9];
    const float* bn1a = (const float*)d_in[10];
    const float* Wn2a = (const float*)d_in[11];
    const float* bn2a = (const float*)d_in[12];
    const float* We1  = (const float*)d_in[13];
    const float* be1  = (const float*)d_in[14];
    const float* We2  = (const float*)d_in[15];
    const float* be2  = (const float*)d_in[16];
    const float* strong = (const float*)d_in[17];
    const float* inits  = (const float*)d_in[18];
    const float* update = (const float*)d_in[19];
    const float* Wu1  = (const float*)d_in[20];
    const float* bu1  = (const float*)d_in[21];
    const float* Wu2  = (const float*)d_in[22];
    const float* bu2  = (const float*)d_in[23];
    const float* ln_g = (const float*)d_in[24];
    const float* ln_b = (const float*)d_in[25];
    const float* Wf1  = (const float*)d_in[26];
    const float* bf1  = (const float*)d_in[27];
    const float* Wf2  = (const float*)d_in[28];
    const float* bf2  = (const float*)d_in[29];
    const float* Wf3  = (const float*)d_in[30];
    const float* bf3  = (const float*)d_in[31];

    k_setup0<<<1, 64>>>(strong, inits, update);
    k_setup1b<<<4, 256>>>();
    k_setup2<<<16, 256>>>();
    k_setup3<<<1, 256>>>();

    mega_kernel<<<N_UE / 8, 256>>>(x_ue, x_ap, edge_attr, edge_src,
                                   Wn1u, bn1u, Wn2u, bn2u,
                                   Wn1a, bn1a, Wn2a, bn2a,
                                   We1, be1, We2, be2,
                                   Wu1, bu1, Wu2, bu2,
                                   ln_g, ln_b, Wf1, bf1, Wf2, bf2, Wf3, bf3,
                                   (float*)d_out);
}

// round 7
// speedup vs baseline: 3.7222x; 3.7222x over previous
#include <cuda_runtime.h>

#define N_UE 8192

// Device globals (alloc-free rule)
__device__ float2 U16g[3][16][16];   // update-block 16x16 unitaries (bits: q3=8, anc=4, q7=2, q8=1)
__device__ float2 RAg[16][8][8];     // T0 applied to basis: [(m0*4+k)][p][q]
__device__ float2 RBg[64][8][8];     // T1 applied: [(m1*16+m0*4+k)][p][q]
__device__ float  g_diag[2048];      // diag of T2: [combo][p]
__device__ float  Cg[768];           // C[a*256 + m2*64 + m1*16 + m0*4 + k]
__device__ float  g_strong[32];      // fused strong-block 4x4 complex unitary, row-major (idx = 2*b_e + b_nb)

// Hermitian basis G_m entry tables: G0=E00, G1=E11, G2=E01+E10, G3=i*E01-i*E10
__constant__ int   cGN[4]     = {1, 1, 2, 2};
__constant__ int   cGa[4][2]  = {{0,0},{1,0},{0,1},{0,1}};
__constant__ int   cGb[4][2]  = {{0,0},{1,0},{1,0},{1,0}};
__constant__ float cGwr[4][2] = {{1,0},{1,0},{1,1},{0,0}};
__constant__ float cGwi[4][2] = {{0,0},{0,0},{0,0},{1,-1}};

__device__ __forceinline__ float2 cadd2(float2 a, float2 b) { return make_float2(a.x + b.x, a.y + b.y); }
__device__ __forceinline__ float2 cmul2(float2 a, float2 b) {
    return make_float2(a.x * b.x - a.y * b.y, a.x * b.y + a.y * b.x);
}
__device__ __forceinline__ float2 cmulc(float2 a, float2 b) {   // a * conj(b)
    return make_float2(a.x * b.x + a.y * b.y, a.y * b.x - a.x * b.y);
}
__device__ __forceinline__ float lrelu(float v) { return v > 0.f ? v : 0.01f * v; }

// system s = 4*b3 + 2*b7 + b8 ; full 4-qubit index with ancilla bit a
__device__ __forceinline__ int fidx(int s, int a) { return ((s & 4) << 1) | (a << 2) | (s & 3); }

__device__ __forceinline__ void rot_to(float* o, float phi, float th, float om)
{
    float c, s, cp, sp, cm, sm;
    __sincosf(0.5f * th, &s, &c);
    __sincosf(0.5f * (phi + om), &sp, &cp);
    __sincosf(0.5f * (phi - om), &sm, &cm);
    o[0] =  c * cp; o[1] = -c * sp;
    o[2] = -s * cm; o[3] = -s * sm;
    o[4] =  s * cm; o[5] = -s * sm;
    o[6] =  c * cp; o[7] =  c * sp;
}

struct cplx { float r, i; };
__device__ void rot2c(cplx* o, float phi, float th, float om)
{
    float m[8]; rot_to(m, phi, th, om);
    o[0] = cplx{m[0], m[1]}; o[1] = cplx{m[2], m[3]};
    o[2] = cplx{m[4], m[5]}; o[3] = cplx{m[6], m[7]};
}
__device__ void lmul4(cplx* U, const cplx* G)   // U <- G @ U
{
    cplx T[16];
    for (int i = 0; i < 4; i++)
        for (int j = 0; j < 4; j++) {
            cplx s{0.f, 0.f};
            for (int k = 0; k < 4; k++) {
                cplx g = G[i * 4 + k], u = U[k * 4 + j];
                s.r += g.r * u.r - g.i * u.i;
                s.i += g.r * u.i + g.i * u.r;
            }
            T[i * 4 + j] = s;
        }
    for (int i = 0; i < 16; i++) U[i] = T[i];
}
__device__ __forceinline__ void zero16(cplx* G) { for (int i = 0; i < 16; i++) G[i] = cplx{0.f, 0.f}; }

// ---------------------------------------------------------------------------
// K0 (1 block, 64 thr): build U16 columns (t<48) and strong 4x4 (t==48).
// ---------------------------------------------------------------------------
__global__ __launch_bounds__(64)
void k_setup0(const float* __restrict__ strong,
              const float* __restrict__ inits,
              const float* __restrict__ update)
{
    int t = threadIdx.x;

    if (t < 48) {
        int i = t >> 4, col = t & 15;
        float2 v[16];
#pragma unroll
        for (int x = 0; x < 16; x++) v[x] = make_float2(x == col ? 1.f : 0.f, 0.f);
        for (int l = 0; l < 2; l++) {
            for (int j = 0; j < 4; j++) {
                float m[8];
                const float* w = update + ((i * 2 + l) * 4 + j) * 3;
                rot_to(m, w[0], w[1], w[2]);
                int M = 8 >> j;
                for (int x = 0; x < 16; x++) if (!(x & M)) {
                    int x1 = x | M;
                    float2 a0 = v[x], a1 = v[x1];
                    v[x]  = make_float2(m[0]*a0.x - m[1]*a0.y + m[2]*a1.x - m[3]*a1.y,
                                        m[0]*a0.y + m[1]*a0.x + m[2]*a1.y + m[3]*a1.x);
                    v[x1] = make_float2(m[4]*a0.x - m[5]*a0.y + m[6]*a1.x - m[7]*a1.y,
                                        m[4]*a0.y + m[5]*a0.x + m[6]*a1.y + m[7]*a1.x);
                }
            }
            const int cm4[4] = {8, 4, 2, 1};
            const int t0m[4] = {4, 2, 1, 8};   // l=0: r=1
            const int t1m[4] = {2, 1, 8, 4};   // l=1: r=2
            for (int j = 0; j < 4; j++) {
                int cm = cm4[j], tm = l ? t1m[j] : t0m[j];
                for (int x = 0; x < 16; x++)
                    if ((x & cm) && (x & tm)) {
                        float2 tmp = v[x]; v[x] = v[x ^ tm]; v[x ^ tm] = tmp;
                    }
            }
        }
        for (int row = 0; row < 16; row++) U16g[i][row][col] = v[row];
    }

    if (t == 48) {
        cplx U[16], G[16], r2[4];
        zero16(U); U[0] = U[5] = U[10] = U[15] = cplx{1.f, 0.f};
        float c, s;
        __sincosf(0.5f * inits[0], &s, &c);        // CRX control=nb target=e
        zero16(G);
        G[0] = cplx{1.f,0.f}; G[10] = cplx{1.f,0.f};
        G[5] = cplx{c,0.f};   G[7]  = cplx{0.f,-s};
        G[13] = cplx{0.f,-s}; G[15] = cplx{c,0.f};
        lmul4(U, G);
        __sincosf(0.5f * inits[1], &s, &c);        // CRY control=e target=nb
        zero16(G);
        G[0] = cplx{1.f,0.f}; G[5] = cplx{1.f,0.f};
        G[10] = cplx{c,0.f};  G[11] = cplx{-s,0.f};
        G[14] = cplx{s,0.f};  G[15] = cplx{c,0.f};
        lmul4(U, G);
        for (int l = 0; l < 2; l++) {
            rot2c(r2, strong[(l*2+0)*3], strong[(l*2+0)*3+1], strong[(l*2+0)*3+2]);  // ROT on e
            zero16(G);
            G[0] = r2[0]; G[2] = r2[1]; G[8] = r2[2]; G[10] = r2[3];
            G[5] = r2[0]; G[7] = r2[1]; G[13] = r2[2]; G[15] = r2[3];
            lmul4(U, G);
            rot2c(r2, strong[(l*2+1)*3], strong[(l*2+1)*3+1], strong[(l*2+1)*3+2]);  // ROT on nb
            zero16(G);
            G[0] = r2[0]; G[1] = r2[1]; G[4] = r2[2]; G[5] = r2[3];
            G[10] = r2[0]; G[11] = r2[1]; G[14] = r2[2]; G[15] = r2[3];
            lmul4(U, G);
            zero16(G);                                         // CX e->nb: swap 2<->3
            G[0] = cplx{1.f,0.f}; G[5] = cplx{1.f,0.f};
            G[11] = cplx{1.f,0.f}; G[14] = cplx{1.f,0.f};
            lmul4(U, G);
            zero16(G);                                         // CX nb->e: swap 1<->3
            G[0] = cplx{1.f,0.f}; G[10] = cplx{1.f,0.f};
            G[7] = cplx{1.f,0.f}; G[13] = cplx{1.f,0.f};
            lmul4(U, G);
        }
        for (int x = 0; x < 16; x++) {
            g_strong[x * 2 + 0] = U[x].r;
            g_strong[x * 2 + 1] = U[x].i;
        }
    }
}

// ---------------------------------------------------------------------------
// K1 (4 blocks x 256): RA[m0*4+k][p][q] = T0(F_k ; G_m0). U16g[0] smem-cached.
// ---------------------------------------------------------------------------
__global__ __launch_bounds__(256)
void k_setup1b()
{
    __shared__ float2 sU[16][16];
    int tt = threadIdx.x;
    sU[tt >> 4][tt & 15] = U16g[0][tt >> 4][tt & 15];
    __syncthreads();

    int t = blockIdx.x * 256 + tt;                // [0, 1024)
    int m0 = (t >> 8) & 3, k = (t >> 6) & 3, p = (t >> 3) & 7, q = t & 7;
    float2 acc = make_float2(0.f, 0.f);
    for (int a = 0; a < 2; a++) {
        int rp = fidx(p, a), rq = fidx(q, a);
        for (int ef = 0; ef < cGN[k]; ef++) {
            int ps = 4 * cGa[k][ef], qs = 4 * cGb[k][ef];
            float2 wf = make_float2(cGwr[k][ef], cGwi[k][ef]);
            for (int eg = 0; eg < cGN[m0]; eg++) {
                float2 wg = make_float2(cGwr[m0][eg], cGwi[m0][eg]);
                float2 u1 = sU[rp][fidx(ps, cGa[m0][eg])];
                float2 u2 = sU[rq][fidx(qs, cGb[m0][eg])];
                acc = cadd2(acc, cmul2(cmul2(wf, wg), cmulc(u1, u2)));
            }
        }
    }
    RAg[m0 * 4 + k][p][q] = acc;
}

// ---------------------------------------------------------------------------
// K2 (16 blocks x 256): block = c0. RB[m1*16+c0] = T1(RA[c0] ; G_m1).
// U16g[1] and RA[c0] smem-cached.
// ---------------------------------------------------------------------------
__global__ __launch_bounds__(256)
void k_setup2()
{
    __shared__ float2 sU[16][16];
    __shared__ float2 sRA[8][8];
    int tt = threadIdx.x;
    int c0 = blockIdx.x;
    sU[tt >> 4][tt & 15] = U16g[1][tt >> 4][tt & 15];
    if (tt < 64) sRA[tt >> 3][tt & 7] = RAg[c0][tt >> 3][tt & 7];
    __syncthreads();

    int m1 = tt >> 6, p = (tt >> 3) & 7, q = tt & 7;
    float2 acc = make_float2(0.f, 0.f);
    for (int a = 0; a < 2; a++) {
        int rp = fidx(p, a), rq = fidx(q, a);
        for (int eg = 0; eg < cGN[m1]; eg++) {
            float2 w = make_float2(cGwr[m1][eg], cGwi[m1][eg]);
            int al = cGa[m1][eg], ar = cGb[m1][eg];
            float2 ssum = make_float2(0.f, 0.f);
#pragma unroll
            for (int ps = 0; ps < 8; ps++) {
                float2 up = sU[rp][fidx(ps, al)];
                float2 ts = make_float2(0.f, 0.f);
#pragma unroll
                for (int qs = 0; qs < 8; qs++)
                    ts = cadd2(ts, cmulc(sRA[ps][qs], sU[rq][fidx(qs, ar)]));
                ssum = cadd2(ssum, cmul2(up, ts));
            }
            acc = cadd2(acc, cmul2(w, ssum));
        }
    }
    RBg[m1 * 16 + c0][p][q] = acc;
}

// ---------------------------------------------------------------------------
// K3a (8 blocks x 256): one diag entry per thread; RBg (32KB) + U16g[2] smem.
// ---------------------------------------------------------------------------
__global__ __launch_bounds__(256)
void k_setup3a()
{
    __shared__ float2 sU[16][16];
    __shared__ float2 sRB[64][8][8];
    int tt = threadIdx.x;
    sU[tt >> 4][tt & 15] = U16g[2][tt >> 4][tt & 15];
    for (int i = tt; i < 64 * 64; i += 256)
        ((float2*)sRB)[i] = ((const float2*)RBg)[i];
    __syncthreads();

    int task = blockIdx.x * 256 + tt;             // [0, 2048)
    int combo = task >> 3, p = task & 7;
    int m2 = combo >> 6, c3 = combo & 63;

    float2 acc = make_float2(0.f, 0.f);
    for (int a = 0; a < 2; a++) {
        int rp = fidx(p, a);
        for (int eg = 0; eg < cGN[m2]; eg++) {
            float2 w = make_float2(cGwr[m2][eg], cGwi[m2][eg]);
            int al = cGa[m2][eg], ar = cGb[m2][eg];
            float2 ssum = make_float2(0.f, 0.f);
#pragma unroll
            for (int ps = 0; ps < 8; ps++) {
                float2 up = sU[rp][fidx(ps, al)];
                float2 ts = make_float2(0.f, 0.f);
#pragma unroll
                for (int qs = 0; qs < 8; qs++)
                    ts = cadd2(ts, cmulc(sRB[c3][ps][qs], sU[rp][fidx(qs, ar)]));
                ssum = cadd2(ssum, cmul2(up, ts));
            }
            acc = cadd2(acc, cmul2(w, ssum));
        }
    }
    g_diag[combo * 8 + p] = acc.x;
}

// ---------------------------------------------------------------------------
// K3b (1 block x 256): Z-contract diag into Cg (768 outputs, 3 per thread).
// ---------------------------------------------------------------------------
__global__ __launch_bounds__(256)
void k_setup3b()
{
    int combo = threadIdx.x;
    float d[8];
#pragma unroll
    for (int p = 0; p < 8; p++) d[p] = g_diag[combo * 8 + p];
#pragma unroll
    for (int a = 0; a < 3; a++) {
        float s = 0.f;
#pragma unroll
        for (int p = 0; p < 8; p++) {
            int bit = (a == 0) ? (p & 4) : (a == 1) ? (p & 2) : (p & 1);
            s += (bit ? -1.f : 1.f) * d[p];
        }
        Cg[a * 256 + combo] = s;
    }
}

// ---------------------------------------------------------------------------
// Warp-cooperative MLP row: x (D floats) -> 2 outputs (same on all lanes)
// ---------------------------------------------------------------------------
template <int D>
__device__ __forceinline__ float2 mlp_row(const float* __restrict__ x,
                                          const float* __restrict__ W1, const float* __restrict__ b1,
                                          const float* __restrict__ W2, const float* __restrict__ b2,
                                          int lane)
{
    float xv[D];
#pragma unroll
    for (int d = 0; d < D; d++) xv[d] = __ldg(x + d);
    float o0 = 0.f, o1 = 0.f;
#pragma unroll
    for (int r = 0; r < 4; r++) {
        int d = lane + 32 * r;
        float h = __ldg(b1 + d);
#pragma unroll
        for (int k = 0; k < D; k++) h = fmaf(xv[k], __ldg(W1 + k * 128 + d), h);
        h = lrelu(h);
        float2 w2 = __ldg((const float2*)(W2 + d * 2));
        o0 = fmaf(h, w2.x, o0);
        o1 = fmaf(h, w2.y, o1);
    }
#pragma unroll
    for (int o = 16; o; o >>= 1) {
        o0 += __shfl_xor_sync(0xFFFFFFFFu, o0, o);
        o1 += __shfl_xor_sync(0xFFFFFFFFu, o1, o);
    }
    return make_float2(o0 + __ldg(b2), o1 + __ldg(b2 + 1));
}

// ---------------------------------------------------------------------------
// Mega kernel: embeddings -> analytic channel contraction -> classifier head.
// ---------------------------------------------------------------------------
__global__ __launch_bounds__(256)
void mega_kernel(const float* __restrict__ x_ue, const float* __restrict__ x_ap,
                 const float* __restrict__ edge_attr, const int* __restrict__ edge_src,
                 const float* __restrict__ Wn1u, const float* __restrict__ bn1u,
                 const float* __restrict__ Wn2u, const float* __restrict__ bn2u,
                 const float* __restrict__ Wn1a, const float* __restrict__ bn1a,
                 const float* __restrict__ Wn2a, const float* __restrict__ bn2a,
                 const float* __restrict__ We1,  const float* __restrict__ be1,
                 const float* __restrict__ We2,  const float* __restrict__ be2,
                 const float* __restrict__ Wu1,  const float* __restrict__ bu1,
                 const float* __restrict__ Wu2,  const float* __restrict__ bu2,
                 const float* __restrict__ ln_g, const float* __restrict__ ln_b,
                 const float* __restrict__ Wf1,  const float* __restrict__ bf1,
                 const float* __restrict__ Wf2,  const float* __restrict__ bf2,
                 const float* __restrict__ Wf3,  const float* __restrict__ bf3,
                 float* __restrict__ out)
{
    int warp = threadIdx.x >> 5;
    int lane = threadIdx.x & 31;
    int n = blockIdx.x * 8 + warp;

    // ---- Phase 1: embeddings ----------------------------------------------
    float a[7], b[7];
#pragma unroll
    for (int q = 0; q < 3; q++) {
        float2 e = mlp_row<4>(edge_attr + (n * 3 + q) * 4, We1, be1, We2, be2, lane);
        a[q] = e.x; b[q] = e.y;
    }
    {
        float2 u = mlp_row<8>(x_ue + n * 8, Wn1u, bn1u, Wn2u, bn2u, lane);
        a[3] = u.x; b[3] = u.y;
    }
#pragma unroll
    for (int i = 0; i < 3; i++) {
        int src = __ldg(&edge_src[n * 3 + i]);
        float2 p = mlp_row<8>(x_ap + src * 8, Wn1a, bn1a, Wn2a, bn2a, lane);
        a[4 + i] = p.x; b[4 + i] = p.y;
    }

    // ---- Phase 2: analytic quantum channel ---------------------------------
    float2 sq[7][2];
#pragma unroll
    for (int q = 0; q < 7; q++) {
        float ca, sa, cb2, sb2;
        __sincosf(0.5f * a[q], &sa, &ca);
        __sincosf(0.5f * b[q], &sb2, &cb2);
        sq[q][0] = make_float2(ca * cb2, -ca * sb2);
        sq[q][1] = make_float2(sa * sb2, -sa * cb2);
    }

    float f0[4];
    {
        float2 u0 = sq[3][0], u1 = sq[3][1];
        f0[0] = u0.x * u0.x + u0.y * u0.y;
        f0[1] = u1.x * u1.x + u1.y * u1.y;
        float2 x01 = cmulc(u0, u1);
        f0[2] = x01.x; f0[3] = x01.y;
    }

    float2 V[16];
    {
        const float4* gp = (const float4*)g_strong;
#pragma unroll
        for (int h = 0; h < 8; h++) {
            float4 x = __ldg(gp + h);
            V[2 * h]     = make_float2(x.x, x.y);
            V[2 * h + 1] = make_float2(x.z, x.w);
        }
    }

    float g[3][4];
#pragma unroll
    for (int i = 0; i < 3; i++) {
        float2 e0 = sq[i][0], e1 = sq[i][1], n0 = sq[4 + i][0], n1 = sq[4 + i][1];
        float2 in4[4] = {cmul2(e0, n0), cmul2(e0, n1), cmul2(e1, n0), cmul2(e1, n1)};
        float2 chi[4];
#pragma unroll
        for (int r = 0; r < 4; r++) {
            float2 s = cmul2(V[r * 4 + 0], in4[0]);
            s = cadd2(s, cmul2(V[r * 4 + 1], in4[1]));
            s = cadd2(s, cmul2(V[r * 4 + 2], in4[2]));
            s = cadd2(s, cmul2(V[r * 4 + 3], in4[3]));
            chi[r] = s;
        }
        // reduced ancilla (nb) state: rho = Tr_e |chi><chi| ; basis idx = 2*b_e + b_nb
        g[i][0] = chi[0].x*chi[0].x + chi[0].y*chi[0].y + chi[2].x*chi[2].x + chi[2].y*chi[2].y;
        g[i][1] = chi[1].x*chi[1].x + chi[1].y*chi[1].y + chi[3].x*chi[3].x + chi[3].y*chi[3].y;
        float2 x01 = cadd2(cmulc(chi[0], chi[1]), cmulc(chi[2], chi[3]));
        g[i][2] = x01.x; g[i][3] = x01.y;
    }

    // contraction: combo c = m2*64 + m1*16 + m0*4 + k ; lane handles c = lane + 32j
    float m3 = 0.f, m7 = 0.f, m8 = 0.f;
#pragma unroll
    for (int j = 0; j < 8; j++) {
        int c = lane + 32 * j;
        float prod = f0[c & 3] * g[0][(c >> 2) & 3] * g[1][(c >> 4) & 3] * g[2][(c >> 6) & 3];
        m3 = fmaf(prod, __ldg(&Cg[c]),       m3);
        m7 = fmaf(prod, __ldg(&Cg[256 + c]), m7);
        m8 = fmaf(prod, __ldg(&Cg[512 + c]), m8);
    }
#pragma unroll
    for (int o = 16; o; o >>= 1) {
        m3 += __shfl_xor_sync(0xFFFFFFFFu, m3, o);
        m7 += __shfl_xor_sync(0xFFFFFFFFu, m7, o);
        m8 += __shfl_xor_sync(0xFFFFFFFFu, m8, o);
    }

    // ---- Phase 3: classifier head ------------------------------------------
    float in5[5] = {a[3], b[3], m3, m7, m8};

    float u0 = 0.f, u1 = 0.f;
#pragma unroll
    for (int r = 0; r < 4; r++) {
        int d = lane + 32 * r;
        float h = __ldg(bu1 + d);
#pragma unroll
        for (int k = 0; k < 5; k++) h = fmaf(in5[k], __ldg(Wu1 + k * 128 + d), h);
        h = lrelu(h);
        float2 w2 = __ldg((const float2*)(Wu2 + d * 2));
        u0 = fmaf(h, w2.x, u0);
        u1 = fmaf(h, w2.y, u1);
    }
#pragma unroll
    for (int o = 16; o; o >>= 1) {
        u0 += __shfl_xor_sync(0xFFFFFFFFu, u0, o);
        u1 += __shfl_xor_sync(0xFFFFFFFFu, u1, o);
    }
    float h0 = in5[0] + u0 + __ldg(bu2);
    float h1 = in5[1] + u1 + __ldg(bu2 + 1);

    float mu = 0.5f * (h0 + h1);
    float d0 = h0 - mu, d1 = h1 - mu;
    float var = 0.5f * (d0 * d0 + d1 * d1);
    float inv = rsqrtf(var + 1e-5f);
    h0 = d0 * inv * __ldg(ln_g) + __ldg(ln_b);
    h1 = d1 * inv * __ldg(ln_g + 1) + __ldg(ln_b + 1);

    float av[4];
#pragma unroll
    for (int r = 0; r < 4; r++) {
        int d = lane + 32 * r;
        av[r] = lrelu(fmaf(h0, __ldg(Wf1 + d), fmaf(h1, __ldg(Wf1 + 128 + d), __ldg(bf1 + d))));
    }

    float bv[4];
#pragma unroll
    for (int r = 0; r < 4; r++) bv[r] = __ldg(bf2 + lane + 32 * r);
    for (int k = 0; k < 128; k++) {
        float ak = __shfl_sync(0xFFFFFFFFu, av[k >> 5], k & 31);
        const float* row = Wf2 + k * 128;
#pragma unroll
        for (int r = 0; r < 4; r++) bv[r] = fmaf(ak, __ldg(row + lane + 32 * r), bv[r]);
    }

    float o0 = 0.f, o1 = 0.f;
#pragma unroll
    for (int r = 0; r < 4; r++) {
        int d = lane + 32 * r;
        float t = lrelu(bv[r]);
        float2 w3 = __ldg((const float2*)(Wf3 + d * 2));
        o0 = fmaf(t, w3.x, o0);
        o1 = fmaf(t, w3.y, o1);
    }
#pragma unroll
    for (int o = 16; o; o >>= 1) {
        o0 += __shfl_xor_sync(0xFFFFFFFFu, o0, o);
        o1 += __shfl_xor_sync(0xFFFFFFFFu, o1, o);
    }
    if (lane == 0) {
        o0 += __ldg(bf3);
        o1 += __ldg(bf3 + 1);
        out[n * 2 + 0] = 1.f / (1.f + __expf(-o0));
        out[n * 2 + 1] = 1.f / (1.f + __expf(-o1));
    }
}

// ---------------------------------------------------------------------------
extern "C" void kernel_launch(void* const* d_in, const int* in_sizes, int n_in,
                              void* d_out, int out_size)
{
    (void)in_sizes; (void)n_in; (void)out_size;
    const float* x_ue      = (const float*)d_in[0];
    const float* x_ap      = (const float*)d_in[1];
    const float* edge_attr = (const float*)d_in[2];
    const int*   edge_src  = (const int*)  d_in[3];
    const float* Wn1u = (const float*)d_in[5];
    const float* bn1u = (const float*)d_in[6];
    const float* Wn2u = (const float*)d_in[7];
    const float* bn2u = (const float*)d_in[8];
    const float* Wn1a = (const float*)d_in[9];
    const float* bn1a = (const float*)d_in[10];
    const float* Wn2a = (const float*)d_in[11];
    const float* bn2a = (const float*)d_in[12];
    const float* We1  = (const float*)d_in[13];
    const float* be1  = (const float*)d_in[14];
    const float* We2  = (const float*)d_in[15];
    const float* be2  = (const float*)d_in[16];
    const float* strong = (const float*)d_in[17];
    const float* inits  = (const float*)d_in[18];
    const float* update = (const float*)d_in[19];
    const float* Wu1  = (const float*)d_in[20];
    const float* bu1  = (const float*)d_in[21];
    const float* Wu2  = (const float*)d_in[22];
    const float* bu2  = (const float*)d_in[23];
    const float* ln_g = (const float*)d_in[24];
    const float* ln_b = (const float*)d_in[25];
    const float* Wf1  = (const float*)d_in[26];
    const float* bf1  = (const float*)d_in[27];
    const float* Wf2  = (const float*)d_in[28];
    const float* bf2  = (const float*)d_in[29];
    const float* Wf3  = (const float*)d_in[30];
    const float* bf3  = (const float*)d_in[31];

    k_setup0<<<1, 64>>>(strong, inits, update);
    k_setup1b<<<4, 256>>>();
    k_setup2<<<16, 256>>>();
    k_setup3a<<<8, 256>>>();
    k_setup3b<<<1, 256>>>();

    mega_kernel<<<N_UE / 8, 256>>>(x_ue, x_ap, edge_attr, edge_src,
                                   Wn1u, bn1u, Wn2u, bn2u,
                                   Wn1a, bn1a, Wn2a, bn2a,
                                   We1, be1, We2, be2,
                                   Wu1, bu1, Wu2, bu2,
                                   ln_g, ln_b, Wf1, bf1, Wf2, bf2, Wf3, bf3,
                                   (float*)d_out);
}

// round 8
// speedup vs baseline: 4.4667x; 1.2000x over previous
#include <cuda_runtime.h>

#define N_UE 8192

// Device globals (alloc-free rule)
__device__ float2 U16g[3][16][16];   // update-block 16x16 unitaries (bits: q3=8, anc=4, q7=2, q8=1)
__device__ float2 RBg[64][8][8];     // T1(T0(F_k)) basis images: [(m1*16+m0*4+k)][p][q]
__device__ float  Cg[768];           // C[a*256 + m2*64 + m1*16 + m0*4 + k]
__device__ float  g_strong[32];      // fused strong-block 4x4 complex unitary, row-major (idx = 2*b_e + b_nb)

// Hermitian basis G_m entry tables: G0=E00, G1=E11, G2=E01+E10, G3=i*E01-i*E10
__constant__ int   cGN[4]     = {1, 1, 2, 2};
__constant__ int   cGa[4][2]  = {{0,0},{1,0},{0,1},{0,1}};
__constant__ int   cGb[4][2]  = {{0,0},{1,0},{1,0},{1,0}};
__constant__ float cGwr[4][2] = {{1,0},{1,0},{1,1},{0,0}};
__constant__ float cGwi[4][2] = {{0,0},{0,0},{0,0},{1,-1}};

__device__ __forceinline__ float2 cadd2(float2 a, float2 b) { return make_float2(a.x + b.x, a.y + b.y); }
__device__ __forceinline__ float2 cmul2(float2 a, float2 b) {
    return make_float2(a.x * b.x - a.y * b.y, a.x * b.y + a.y * b.x);
}
__device__ __forceinline__ float2 cmulc(float2 a, float2 b) {   // a * conj(b)
    return make_float2(a.x * b.x + a.y * b.y, a.y * b.x - a.x * b.y);
}
__device__ __forceinline__ float lrelu(float v) { return v > 0.f ? v : 0.01f * v; }

// system s = 4*b3 + 2*b7 + b8 ; full 4-qubit index with ancilla bit a
__device__ __forceinline__ int fidx(int s, int a) { return ((s & 4) << 1) | (a << 2) | (s & 3); }

__device__ __forceinline__ void rot_to(float* o, float phi, float th, float om)
{
    float c, s, cp, sp, cm, sm;
    __sincosf(0.5f * th, &s, &c);
    __sincosf(0.5f * (phi + om), &sp, &cp);
    __sincosf(0.5f * (phi - om), &sm, &cm);
    o[0] =  c * cp; o[1] = -c * sp;
    o[2] = -s * cm; o[3] = -s * sm;
    o[4] =  s * cm; o[5] = -s * sm;
    o[6] =  c * cp; o[7] =  c * sp;
}

struct cplx { float r, i; };
__device__ void rot2c(cplx* o, float phi, float th, float om)
{
    float m[8]; rot_to(m, phi, th, om);
    o[0] = cplx{m[0], m[1]}; o[1] = cplx{m[2], m[3]};
    o[2] = cplx{m[4], m[5]}; o[3] = cplx{m[6], m[7]};
}
__device__ void lmul4(cplx* U, const cplx* G)   // U <- G @ U
{
    cplx T[16];
    for (int i = 0; i < 4; i++)
        for (int j = 0; j < 4; j++) {
            cplx s{0.f, 0.f};
            for (int k = 0; k < 4; k++) {
                cplx g = G[i * 4 + k], u = U[k * 4 + j];
                s.r += g.r * u.r - g.i * u.i;
                s.i += g.r * u.i + g.i * u.r;
            }
            T[i * 4 + j] = s;
        }
    for (int i = 0; i < 16; i++) U[i] = T[i];
}
__device__ __forceinline__ void zero16(cplx* G) { for (int i = 0; i < 16; i++) G[i] = cplx{0.f, 0.f}; }

// ---------------------------------------------------------------------------
// K0 (1 block, 64 thr): build U16 columns (t<48) and strong 4x4 (t==48).
// ---------------------------------------------------------------------------
__global__ __launch_bounds__(64)
void k_setup0(const float* __restrict__ strong,
              const float* __restrict__ inits,
              const float* __restrict__ update)
{
    int t = threadIdx.x;

    if (t < 48) {
        int i = t >> 4, col = t & 15;
        float2 v[16];
#pragma unroll
        for (int x = 0; x < 16; x++) v[x] = make_float2(x == col ? 1.f : 0.f, 0.f);
        for (int l = 0; l < 2; l++) {
            for (int j = 0; j < 4; j++) {
                float m[8];
                const float* w = update + ((i * 2 + l) * 4 + j) * 3;
                rot_to(m, w[0], w[1], w[2]);
                int M = 8 >> j;
                for (int x = 0; x < 16; x++) if (!(x & M)) {
                    int x1 = x | M;
                    float2 a0 = v[x], a1 = v[x1];
                    v[x]  = make_float2(m[0]*a0.x - m[1]*a0.y + m[2]*a1.x - m[3]*a1.y,
                                        m[0]*a0.y + m[1]*a0.x + m[2]*a1.y + m[3]*a1.x);
                    v[x1] = make_float2(m[4]*a0.x - m[5]*a0.y + m[6]*a1.x - m[7]*a1.y,
                                        m[4]*a0.y + m[5]*a0.x + m[6]*a1.y + m[7]*a1.x);
                }
            }
            const int cm4[4] = {8, 4, 2, 1};
            const int t0m[4] = {4, 2, 1, 8};   // l=0: r=1
            const int t1m[4] = {2, 1, 8, 4};   // l=1: r=2
            for (int j = 0; j < 4; j++) {
                int cm = cm4[j], tm = l ? t1m[j] : t0m[j];
                for (int x = 0; x < 16; x++)
                    if ((x & cm) && (x & tm)) {
                        float2 tmp = v[x]; v[x] = v[x ^ tm]; v[x ^ tm] = tmp;
                    }
            }
        }
        for (int row = 0; row < 16; row++) U16g[i][row][col] = v[row];
    }

    if (t == 48) {
        cplx U[16], G[16], r2[4];
        zero16(U); U[0] = U[5] = U[10] = U[15] = cplx{1.f, 0.f};
        float c, s;
        __sincosf(0.5f * inits[0], &s, &c);        // CRX control=nb target=e
        zero16(G);
        G[0] = cplx{1.f,0.f}; G[10] = cplx{1.f,0.f};
        G[5] = cplx{c,0.f};   G[7]  = cplx{0.f,-s};
        G[13] = cplx{0.f,-s}; G[15] = cplx{c,0.f};
        lmul4(U, G);
        __sincosf(0.5f * inits[1], &s, &c);        // CRY control=e target=nb
        zero16(G);
        G[0] = cplx{1.f,0.f}; G[5] = cplx{1.f,0.f};
        G[10] = cplx{c,0.f};  G[11] = cplx{-s,0.f};
        G[14] = cplx{s,0.f};  G[15] = cplx{c,0.f};
        lmul4(U, G);
        for (int l = 0; l < 2; l++) {
            rot2c(r2, strong[(l*2+0)*3], strong[(l*2+0)*3+1], strong[(l*2+0)*3+2]);  // ROT on e
            zero16(G);
            G[0] = r2[0]; G[2] = r2[1]; G[8] = r2[2]; G[10] = r2[3];
            G[5] = r2[0]; G[7] = r2[1]; G[13] = r2[2]; G[15] = r2[3];
            lmul4(U, G);
            rot2c(r2, strong[(l*2+1)*3], strong[(l*2+1)*3+1], strong[(l*2+1)*3+2]);  // ROT on nb
            zero16(G);
            G[0] = r2[0]; G[1] = r2[1]; G[4] = r2[2]; G[5] = r2[3];
            G[10] = r2[0]; G[11] = r2[1]; G[14] = r2[2]; G[15] = r2[3];
            lmul4(U, G);
            zero16(G);                                         // CX e->nb: swap 2<->3
            G[0] = cplx{1.f,0.f}; G[5] = cplx{1.f,0.f};
            G[11] = cplx{1.f,0.f}; G[14] = cplx{1.f,0.f};
            lmul4(U, G);
            zero16(G);                                         // CX nb->e: swap 1<->3
            G[0] = cplx{1.f,0.f}; G[10] = cplx{1.f,0.f};
            G[7] = cplx{1.f,0.f}; G[13] = cplx{1.f,0.f};
            lmul4(U, G);
        }
        for (int x = 0; x < 16; x++) {
            g_strong[x * 2 + 0] = U[x].r;
            g_strong[x * 2 + 1] = U[x].i;
        }
    }
}

// ---------------------------------------------------------------------------
// k_rb (16 blocks x 256): block c0 computes RA[c0] in prologue, then
// RB[m1*16+c0] = T1(RA[c0]; G_m1). All operands smem-resident.
// ---------------------------------------------------------------------------
__global__ __launch_bounds__(256)
void k_rb()
{
    __shared__ float2 sU0[16][16];
    __shared__ float2 sU1[16][16];
    __shared__ float2 sRA[8][8];
    int tt = threadIdx.x;
    int c0 = blockIdx.x;                          // m0*4 + k
    sU0[tt >> 4][tt & 15] = U16g[0][tt >> 4][tt & 15];
    sU1[tt >> 4][tt & 15] = U16g[1][tt >> 4][tt & 15];
    __syncthreads();

    // RA prologue (threads 0..63): RA[c0][p][q] = T0(F_k ; G_m0)
    if (tt < 64) {
        int m0 = c0 >> 2, k = c0 & 3, p = tt >> 3, q = tt & 7;
        float2 acc = make_float2(0.f, 0.f);
        for (int a = 0; a < 2; a++) {
            int rp = fidx(p, a), rq = fidx(q, a);
            for (int ef = 0; ef < cGN[k]; ef++) {
                int ps = 4 * cGa[k][ef], qs = 4 * cGb[k][ef];
                float2 wf = make_float2(cGwr[k][ef], cGwi[k][ef]);
                for (int eg = 0; eg < cGN[m0]; eg++) {
                    float2 wg = make_float2(cGwr[m0][eg], cGwi[m0][eg]);
                    float2 u1 = sU0[rp][fidx(ps, cGa[m0][eg])];
                    float2 u2 = sU0[rq][fidx(qs, cGb[m0][eg])];
                    acc = cadd2(acc, cmul2(cmul2(wf, wg), cmulc(u1, u2)));
                }
            }
        }
        sRA[p][q] = acc;
    }
    __syncthreads();

    // RB main: thread -> (m1 = tt>>6, p = (tt>>3)&7, q = tt&7)
    int m1 = tt >> 6, p = (tt >> 3) & 7, q = tt & 7;
    float2 acc = make_float2(0.f, 0.f);
    for (int a = 0; a < 2; a++) {
        int rp = fidx(p, a), rq = fidx(q, a);
        for (int eg = 0; eg < cGN[m1]; eg++) {
            float2 w = make_float2(cGwr[m1][eg], cGwi[m1][eg]);
            int al = cGa[m1][eg], ar = cGb[m1][eg];
            float2 ssum = make_float2(0.f, 0.f);
#pragma unroll
            for (int ps = 0; ps < 8; ps++) {
                float2 up = sU1[rp][fidx(ps, al)];
                float2 ts = make_float2(0.f, 0.f);
#pragma unroll
                for (int qs = 0; qs < 8; qs++)
                    ts = cadd2(ts, cmulc(sRA[ps][qs], sU1[rq][fidx(qs, ar)]));
                ssum = cadd2(ssum, cmul2(up, ts));
            }
            acc = cadd2(acc, cmul2(w, ssum));
        }
    }
    RBg[m1 * 16 + c0][p][q] = acc;
}

// ---------------------------------------------------------------------------
// k_c (3 blocks x 256): block a. Build K[a][m2][ps][qs] (256 entries, one per
// thread), then Cg[a*256 + c] = Re<K[m2], RB[c3]>_F  (one output per thread).
// ---------------------------------------------------------------------------
__global__ __launch_bounds__(256)
void k_c()
{
    __shared__ float2 sU[16][16];
    __shared__ float2 sK[4][8][8];
    __shared__ float2 sRB[64][8][8];
    int tt = threadIdx.x;
    int a = blockIdx.x;
    sU[tt >> 4][tt & 15] = U16g[2][tt >> 4][tt & 15];
    for (int i = tt; i < 64 * 64; i += 256)
        ((float2*)sRB)[i] = ((const float2*)RBg)[i];
    __syncthreads();

    // K build: thread -> (m2 = tt>>6, ps = (tt>>3)&7, qs = tt&7)
    {
        int m2 = tt >> 6, ps = (tt >> 3) & 7, qs = tt & 7;
        float2 acc = make_float2(0.f, 0.f);
        for (int p = 0; p < 8; p++) {
            int bit = (a == 0) ? (p & 4) : (a == 1) ? (p & 2) : (p & 1);
            float z = bit ? -1.f : 1.f;
            for (int a2 = 0; a2 < 2; a2++) {
                int rp = fidx(p, a2);
                for (int eg = 0; eg < cGN[m2]; eg++) {
                    float2 w = make_float2(cGwr[m2][eg], cGwi[m2][eg]);
                    float2 u1 = sU[rp][fidx(ps, cGa[m2][eg])];
                    float2 u2 = sU[rp][fidx(qs, cGb[m2][eg])];
                    float2 term = cmul2(w, cmulc(u1, u2));
                    acc.x += z * term.x;
                    acc.y += z * term.y;
                }
            }
        }
        sK[tt >> 6][(tt >> 3) & 7][tt & 7] = acc;
    }
    __syncthreads();

    // contraction: thread = combo c; m2 = c>>6, c3 = c&63
    {
        int m2 = tt >> 6, c3 = tt & 63;
        float s = 0.f;
#pragma unroll
        for (int ps = 0; ps < 8; ps++)
#pragma unroll
            for (int qs = 0; qs < 8; qs++) {
                float2 kk = sK[m2][ps][qs];
                float2 rb = sRB[c3][ps][qs];
                s += kk.x * rb.x - kk.y * rb.y;
            }
        Cg[a * 256 + tt] = s;
    }
}

// ---------------------------------------------------------------------------
// Warp-cooperative MLP row: x (D floats) -> 2 outputs (same on all lanes)
// ---------------------------------------------------------------------------
template <int D>
__device__ __forceinline__ float2 mlp_row(const float* __restrict__ x,
                                          const float* __restrict__ W1, const float* __restrict__ b1,
                                          const float* __restrict__ W2, const float* __restrict__ b2,
                                          int lane)
{
    float xv[D];
#pragma unroll
    for (int d = 0; d < D; d++) xv[d] = __ldg(x + d);
    float o0 = 0.f, o1 = 0.f;
#pragma unroll
    for (int r = 0; r < 4; r++) {
        int d = lane + 32 * r;
        float h = __ldg(b1 + d);
#pragma unroll
        for (int k = 0; k < D; k++) h = fmaf(xv[k], __ldg(W1 + k * 128 + d), h);
        h = lrelu(h);
        float2 w2 = __ldg((const float2*)(W2 + d * 2));
        o0 = fmaf(h, w2.x, o0);
        o1 = fmaf(h, w2.y, o1);
    }
#pragma unroll
    for (int o = 16; o; o >>= 1) {
        o0 += __shfl_xor_sync(0xFFFFFFFFu, o0, o);
        o1 += __shfl_xor_sync(0xFFFFFFFFu, o1, o);
    }
    return make_float2(o0 + __ldg(b2), o1 + __ldg(b2 + 1));
}

// ---------------------------------------------------------------------------
// Mega kernel: embeddings -> analytic channel -> head.
// Block = 8 nodes. The Wf2 layer is block-cooperative: av activations for the
// 8 nodes go to smem [128][8]; each thread then accumulates 4 nodes against
// one Wf2 column (Wf2 read 2x per block instead of 8x).
// ---------------------------------------------------------------------------
__global__ __launch_bounds__(256)
void mega_kernel(const float* __restrict__ x_ue, const float* __restrict__ x_ap,
                 const float* __restrict__ edge_attr, const int* __restrict__ edge_src,
                 const float* __restrict__ Wn1u, const float* __restrict__ bn1u,
                 const float* __restrict__ Wn2u, const float* __restrict__ bn2u,
                 const float* __restrict__ Wn1a, const float* __restrict__ bn1a,
                 const float* __restrict__ Wn2a, const float* __restrict__ bn2a,
                 const float* __restrict__ We1,  const float* __restrict__ be1,
                 const float* __restrict__ We2,  const float* __restrict__ be2,
                 const float* __restrict__ Wu1,  const float* __restrict__ bu1,
                 const float* __restrict__ Wu2,  const float* __restrict__ bu2,
                 const float* __restrict__ ln_g, const float* __restrict__ ln_b,
                 const float* __restrict__ Wf1,  const float* __restrict__ bf1,
                 const float* __restrict__ Wf2,  const float* __restrict__ bf2,
                 const float* __restrict__ Wf3,  const float* __restrict__ bf3,
                 float* __restrict__ out)
{
    __shared__ float s_av[128][8];          // [hidden dim][node-in-block]
    __shared__ float s_red[8][4][2];        // [warp][node-j][out]

    int warp = threadIdx.x >> 5;
    int lane = threadIdx.x & 31;
    int n = blockIdx.x * 8 + warp;

    // ---- Phase 1: embeddings ----------------------------------------------
    float a[7], b[7];
#pragma unroll
    for (int q = 0; q < 3; q++) {
        float2 e = mlp_row<4>(edge_attr + (n * 3 + q) * 4, We1, be1, We2, be2, lane);
        a[q] = e.x; b[q] = e.y;
    }
    {
        float2 u = mlp_row<8>(x_ue + n * 8, Wn1u, bn1u, Wn2u, bn2u, lane);
        a[3] = u.x; b[3] = u.y;
    }
#pragma unroll
    for (int i = 0; i < 3; i++) {
        int src = __ldg(&edge_src[n * 3 + i]);
        float2 p = mlp_row<8>(x_ap + src * 8, Wn1a, bn1a, Wn2a, bn2a, lane);
        a[4 + i] = p.x; b[4 + i] = p.y;
    }

    // ---- Phase 2: analytic quantum channel ---------------------------------
    float2 sq[7][2];
#pragma unroll
    for (int q = 0; q < 7; q++) {
        float ca, sa, cb2, sb2;
        __sincosf(0.5f * a[q], &sa, &ca);
        __sincosf(0.5f * b[q], &sb2, &cb2);
        sq[q][0] = make_float2(ca * cb2, -ca * sb2);
        sq[q][1] = make_float2(sa * sb2, -sa * cb2);
    }

    float f0[4];
    {
        float2 u0 = sq[3][0], u1 = sq[3][1];
        f0[0] = u0.x * u0.x + u0.y * u0.y;
        f0[1] = u1.x * u1.x + u1.y * u1.y;
        float2 x01 = cmulc(u0, u1);
        f0[2] = x01.x; f0[3] = x01.y;
    }

    float2 V[16];
    {
        const float4* gp = (const float4*)g_strong;
#pragma unroll
        for (int h = 0; h < 8; h++) {
            float4 x = __ldg(gp + h);
            V[2 * h]     = make_float2(x.x, x.y);
            V[2 * h + 1] = make_float2(x.z, x.w);
        }
    }

    float g[3][4];
#pragma unroll
    for (int i = 0; i < 3; i++) {
        float2 e0 = sq[i][0], e1 = sq[i][1], n0 = sq[4 + i][0], n1 = sq[4 + i][1];
        float2 in4[4] = {cmul2(e0, n0), cmul2(e0, n1), cmul2(e1, n0), cmul2(e1, n1)};
        float2 chi[4];
#pragma unroll
        for (int r = 0; r < 4; r++) {
            float2 s = cmul2(V[r * 4 + 0], in4[0]);
            s = cadd2(s, cmul2(V[r * 4 + 1], in4[1]));
            s = cadd2(s, cmul2(V[r * 4 + 2], in4[2]));
            s = cadd2(s, cmul2(V[r * 4 + 3], in4[3]));
            chi[r] = s;
        }
        g[i][0] = chi[0].x*chi[0].x + chi[0].y*chi[0].y + chi[2].x*chi[2].x + chi[2].y*chi[2].y;
        g[i][1] = chi[1].x*chi[1].x + chi[1].y*chi[1].y + chi[3].x*chi[3].x + chi[3].y*chi[3].y;
        float2 x01 = cadd2(cmulc(chi[0], chi[1]), cmulc(chi[2], chi[3]));
        g[i][2] = x01.x; g[i][3] = x01.y;
    }

    float m3 = 0.f, m7 = 0.f, m8 = 0.f;
#pragma unroll
    for (int j = 0; j < 8; j++) {
        int c = lane + 32 * j;
        float prod = f0[c & 3] * g[0][(c >> 2) & 3] * g[1][(c >> 4) & 3] * g[2][(c >> 6) & 3];
        m3 = fmaf(prod, __ldg(&Cg[c]),       m3);
        m7 = fmaf(prod, __ldg(&Cg[256 + c]), m7);
        m8 = fmaf(prod, __ldg(&Cg[512 + c]), m8);
    }
#pragma unroll
    for (int o = 16; o; o >>= 1) {
        m3 += __shfl_xor_sync(0xFFFFFFFFu, m3, o);
        m7 += __shfl_xor_sync(0xFFFFFFFFu, m7, o);
        m8 += __shfl_xor_sync(0xFFFFFFFFu, m8, o);
    }

    // ---- Phase 3a (per-warp): Wu1 layer, residual, LayerNorm, Wf1 -> s_av --
    float in5[5] = {a[3], b[3], m3, m7, m8};

    float u0 = 0.f, u1 = 0.f;
#pragma unroll
    for (int r = 0; r < 4; r++) {
        int d = lane + 32 * r;
        float h = __ldg(bu1 + d);
#pragma unroll
        for (int k = 0; k < 5; k++) h = fmaf(in5[k], __ldg(Wu1 + k * 128 + d), h);
        h = lrelu(h);
        float2 w2 = __ldg((const float2*)(Wu2 + d * 2));
        u0 = fmaf(h, w2.x, u0);
        u1 = fmaf(h, w2.y, u1);
    }
#pragma unroll
    for (int o = 16; o; o >>= 1) {
        u0 += __shfl_xor_sync(0xFFFFFFFFu, u0, o);
        u1 += __shfl_xor_sync(0xFFFFFFFFu, u1, o);
    }
    float h0 = in5[0] + u0 + __ldg(bu2);
    float h1 = in5[1] + u1 + __ldg(bu2 + 1);

    float mu = 0.5f * (h0 + h1);
    float d0 = h0 - mu, d1 = h1 - mu;
    float var = 0.5f * (d0 * d0 + d1 * d1);
    float inv = rsqrtf(var + 1e-5f);
    h0 = d0 * inv * __ldg(ln_g) + __ldg(ln_b);
    h1 = d1 * inv * __ldg(ln_g + 1) + __ldg(ln_b + 1);

#pragma unroll
    for (int r = 0; r < 4; r++) {
        int d = lane + 32 * r;
        float av = lrelu(fmaf(h0, __ldg(Wf1 + d), fmaf(h1, __ldg(Wf1 + 128 + d), __ldg(bf1 + d))));
        s_av[d][warp] = av;
    }
    __syncthreads();

    // ---- Phase 3b (block-cooperative): Wf2 GEMM for 8 nodes ----------------
    // thread: dim d = lane + 32*(warp&3); node group ng = warp>>2 (nodes 4ng..4ng+3)
    int dd = lane + 32 * (warp & 3);
    int ng = warp >> 2;
    float acc0, acc1, acc2, acc3;
    acc0 = acc1 = acc2 = acc3 = __ldg(bf2 + dd);
    const float4* avp = (const float4*)&s_av[0][0];
    for (int k = 0; k < 128; k++) {
        float4 av4 = avp[k * 2 + ng];            // s_av[k][4*ng .. 4*ng+3] broadcast
        float wv = __ldg(Wf2 + k * 128 + dd);
        acc0 = fmaf(av4.x, wv, acc0);
        acc1 = fmaf(av4.y, wv, acc1);
        acc2 = fmaf(av4.z, wv, acc2);
        acc3 = fmaf(av4.w, wv, acc3);
    }

    // lrelu + Wf3 partials, lane-reduce
    float2 w3 = __ldg((const float2*)(Wf3 + dd * 2));
    float p00 = lrelu(acc0), p10 = lrelu(acc1), p20 = lrelu(acc2), p30 = lrelu(acc3);
    float oa0 = p00 * w3.x, ob0 = p00 * w3.y;
    float oa1 = p10 * w3.x, ob1 = p10 * w3.y;
    float oa2 = p20 * w3.x, ob2 = p20 * w3.y;
    float oa3 = p30 * w3.x, ob3 = p30 * w3.y;
#pragma unroll
    for (int o = 16; o; o >>= 1) {
        oa0 += __shfl_xor_sync(0xFFFFFFFFu, oa0, o);
        ob0 += __shfl_xor_sync(0xFFFFFFFFu, ob0, o);
        oa1 += __shfl_xor_sync(0xFFFFFFFFu, oa1, o);
        ob1 += __shfl_xor_sync(0xFFFFFFFFu, ob1, o);
        oa2 += __shfl_xor_sync(0xFFFFFFFFu, oa2, o);
        ob2 += __shfl_xor_sync(0xFFFFFFFFu, ob2, o);
        oa3 += __shfl_xor_sync(0xFFFFFFFFu, oa3, o);
        ob3 += __shfl_xor_sync(0xFFFFFFFFu, ob3, o);
    }
    if (lane == 0) {
        s_red[warp][0][0] = oa0; s_red[warp][0][1] = ob0;
        s_red[warp][1][0] = oa1; s_red[warp][1][1] = ob1;
        s_red[warp][2][0] = oa2; s_red[warp][2][1] = ob2;
        s_red[warp][3][0] = oa3; s_red[warp][3][1] = ob3;
    }
    __syncthreads();

    // finalize: 16 threads -> (node, out)
    if (threadIdx.x < 16) {
        int nn = threadIdx.x >> 1;               // node in block 0..7
        int oo = threadIdx.x & 1;
        int g2 = nn >> 2, j = nn & 3;
        float s = s_red[g2 * 4 + 0][j][oo] + s_red[g2 * 4 + 1][j][oo]
                + s_red[g2 * 4 + 2][j][oo] + s_red[g2 * 4 + 3][j][oo]
                + __ldg(bf3 + oo);
        out[(blockIdx.x * 8 + nn) * 2 + oo] = 1.f / (1.f + __expf(-s));
    }
}

// ---------------------------------------------------------------------------
extern "C" void kernel_launch(void* const* d_in, const int* in_sizes, int n_in,
                              void* d_out, int out_size)
{
    (void)in_sizes; (void)n_in; (void)out_size;
    const float* x_ue      = (const float*)d_in[0];
    const float* x_ap      = (const float*)d_in[1];
    const float* edge_attr = (const float*)d_in[2];
    const int*   edge_src  = (const int*)  d_in[3];
    const float* Wn1u = (const float*)d_in[5];
    const float* bn1u = (const float*)d_in[6];
    const float* Wn2u = (const float*)d_in[7];
    const float* bn2u = (const float*)d_in[8];
    const float* Wn1a = (const float*)d_in[9];
    const float* bn1a = (const float*)d_in[10];
    const float* Wn2a = (const float*)d_in[11];
    const float* bn2a = (const float*)d_in[12];
    const float* We1  = (const float*)d_in[13];
    const float* be1  = (const float*)d_in[14];
    const float* We2  = (const float*)d_in[15];
    const float* be2  = (const float*)d_in[16];
    const float* strong = (const float*)d_in[17];
    const float* inits  = (const float*)d_in[18];
    const float* update = (const float*)d_in[19];
    const float* Wu1  = (const float*)d_in[20];
    const float* bu1  = (const float*)d_in[21];
    const float* Wu2  = (const float*)d_in[22];
    const float* bu2  = (const float*)d_in[23];
    const float* ln_g = (const float*)d_in[24];
    const float* ln_b = (const float*)d_in[25];
    const float* Wf1  = (const float*)d_in[26];
    const float* bf1  = (const float*)d_in[27];
    const float* Wf2  = (const float*)d_in[28];
    const float* bf2  = (const float*)d_in[29];
    const float* Wf3  = (const float*)d_in[30];
    const float* bf3  = (const float*)d_in[31];

    k_setup0<<<1, 64>>>(strong, inits, update);
    k_rb<<<16, 256>>>();
    k_c<<<3, 256>>>();

    mega_kernel<<<N_UE / 8, 256>>>(x_ue, x_ap, edge_attr, edge_src,
                                   Wn1u, bn1u, Wn2u, bn2u,
                                   Wn1a, bn1a, Wn2a, bn2a,
                                   We1, be1, We2, be2,
                                   Wu1, bu1, Wu2, bu2,
                                   ln_g, ln_b, Wf1, bf1, Wf2, bf2, Wf3, bf3,
                                   (float*)d_out);
}